// round 3
// baseline (speedup 1.0000x reference)
#include <cuda_runtime.h>
#include <cuda_bf16.h>
#include <cstdint>

// activation (16, 128, 114, 114) float32.
// Channels  0..31  : inactive (copy)
// Channels 32..79  : 2x2 block-sign ReLU
// Channels 80..127 : 4x4 block-sign ReLU
//
// Sign chain (exact):
//   s = int64(trunc(f32 block sum)); mean = s >> log2(n);
//   q = int16(mean >> 5); sign = q >= 0; out = in * sign
//
// Alignment facts (row = 456 B):
//   image base: img*51984 B, 51984 % 16 == 0  -> 16B aligned
//   even rows (r*456, r even): 16B aligned; odd rows: +8 B.

#define H_DIM 114
#define W_DIM 114
#define IMG_ELEMS (H_DIM * W_DIM)   // 12996

__device__ __forceinline__ float sign_mul_2x2(float sum) {
    long long s = (long long)sum;   // trunc toward zero
    long long mean = s >> 2;        // floor div 4
    short q = (short)(mean >> 5);
    return (q >= 0) ? 1.0f : 0.0f;
}

__device__ __forceinline__ float sign_mul_4x4(float sum) {
    long long s = (long long)sum;
    long long mean = s >> 4;        // floor div 16
    short q = (short)(mean >> 5);
    return (q >= 0) ? 1.0f : 0.0f;
}

__global__ void __launch_bounds__(256)
block_relu_kernel(const float* __restrict__ in, float* __restrict__ out) {
    const int img = blockIdx.x;            // n*128 + c
    const int c = img & 127;
    const size_t base = (size_t)img * IMG_ELEMS;
    const float* __restrict__ src = in + base;
    float* __restrict__ dst = out + base;
    const int t = threadIdx.x;
    const int nt = blockDim.x;

    if (c < 32) {
        // ---- copy, float4 ----
        const float4* __restrict__ s4 = (const float4*)src;
        float4* __restrict__ d4 = (float4*)dst;
        #pragma unroll 4
        for (int i = t; i < IMG_ELEMS / 4; i += nt) {   // 3249
            d4[i] = s4[i];
        }
    } else if (c < 80) {
        // ---- 2x2 blocks: 57 block-rows x 57 blocks.
        // Pair blocks horizontally: per row 28 float4-pairs + 1 float2 tail.
        // Work item i in [0, 57*29): bi = i/29, k = i%29.
        #pragma unroll 2
        for (int i = t; i < 57 * 29; i += nt) {
            const int bi = i / 29;
            const int k = i - bi * 29;
            const int r0 = 2 * bi;
            const float* rowA = src + (size_t)r0 * W_DIM;       // 16B aligned
            const float* rowB = rowA + W_DIM;                   // +8 misaligned
            float* rowAo = dst + (size_t)r0 * W_DIM;
            float* rowBo = rowAo + W_DIM;
            if (k < 28) {
                // two blocks: columns [4k, 4k+4)
                float4 a  = *(const float4*)(rowA + 4 * k);
                float2 b0 = *(const float2*)(rowB + 4 * k);
                float2 b1 = *(const float2*)(rowB + 4 * k + 2);
                // per-block accumulation order identical to scalar version:
                float sum0 = a.x + a.y + b0.x + b0.y;
                float sum1 = a.z + a.w + b1.x + b1.y;
                float m0 = sign_mul_2x2(sum0);
                float m1 = sign_mul_2x2(sum1);
                *(float4*)(rowAo + 4 * k) =
                    make_float4(a.x * m0, a.y * m0, a.z * m1, a.w * m1);
                *(float2*)(rowBo + 4 * k)     = make_float2(b0.x * m0, b0.y * m0);
                *(float2*)(rowBo + 4 * k + 2) = make_float2(b1.x * m1, b1.y * m1);
            } else {
                // tail block: columns [112, 114)
                float2 a = *(const float2*)(rowA + 112);
                float2 b = *(const float2*)(rowB + 112);
                float sum = a.x + a.y + b.x + b.y;
                float m = sign_mul_2x2(sum);
                *(float2*)(rowAo + 112) = make_float2(a.x * m, a.y * m);
                *(float2*)(rowBo + 112) = make_float2(b.x * m, b.y * m);
            }
        }
    } else {
        // ---- 4x4 blocks: 29 x 29 = 841; block (28, *) has 2 rows, (*, 28) has 2 cols.
        #pragma unroll 2
        for (int b = t; b < 29 * 29; b += nt) {
            const int bi = b / 29;
            const int bj = b - bi * 29;
            const int r0 = 4 * bi;
            const int c0 = 4 * bj;

            if (bi < 28 && bj < 28) {
                // interior: even rows (r0, r0+2) 16B aligned -> float4; odd rows float2 pairs
                const float* p0 = src + (size_t)r0 * W_DIM + c0;
                float4 v0 = *(const float4*)(p0);                       // row 0
                float2 v1a = *(const float2*)(p0 + W_DIM);              // row 1
                float2 v1b = *(const float2*)(p0 + W_DIM + 2);
                float4 v2 = *(const float4*)(p0 + 2 * W_DIM);           // row 2
                float2 v3a = *(const float2*)(p0 + 3 * W_DIM);          // row 3
                float2 v3b = *(const float2*)(p0 + 3 * W_DIM + 2);
                // row-major sequential accumulation (same order as scalar version)
                float sum = v0.x + v0.y + v0.z + v0.w
                          + v1a.x + v1a.y + v1b.x + v1b.y
                          + v2.x + v2.y + v2.z + v2.w
                          + v3a.x + v3a.y + v3b.x + v3b.y;
                float m = sign_mul_4x4(sum);
                float* q0 = dst + (size_t)r0 * W_DIM + c0;
                *(float4*)(q0) = make_float4(v0.x * m, v0.y * m, v0.z * m, v0.w * m);
                *(float2*)(q0 + W_DIM)     = make_float2(v1a.x * m, v1a.y * m);
                *(float2*)(q0 + W_DIM + 2) = make_float2(v1b.x * m, v1b.y * m);
                *(float4*)(q0 + 2 * W_DIM) = make_float4(v2.x * m, v2.y * m, v2.z * m, v2.w * m);
                *(float2*)(q0 + 3 * W_DIM)     = make_float2(v3a.x * m, v3a.y * m);
                *(float2*)(q0 + 3 * W_DIM + 2) = make_float2(v3b.x * m, v3b.y * m);
            } else {
                // edge blocks: guarded float2 path (pad contributes 0)
                const int nrows = (r0 + 4 <= H_DIM) ? 4 : (H_DIM - r0);  // 4 or 2
                const bool full = (c0 + 4 <= W_DIM);
                float2 v[4][2];
                float sum = 0.0f;
                #pragma unroll
                for (int r = 0; r < 4; r++) {
                    if (r < nrows) {
                        const float2* p = (const float2*)(src + (size_t)(r0 + r) * W_DIM + c0);
                        v[r][0] = p[0];
                        sum += v[r][0].x + v[r][0].y;
                        if (full) {
                            v[r][1] = p[1];
                            sum += v[r][1].x + v[r][1].y;
                        }
                    }
                }
                float m = sign_mul_4x4(sum);
                #pragma unroll
                for (int r = 0; r < 4; r++) {
                    if (r < nrows) {
                        float2* q = (float2*)(dst + (size_t)(r0 + r) * W_DIM + c0);
                        q[0] = make_float2(v[r][0].x * m, v[r][0].y * m);
                        if (full) {
                            q[1] = make_float2(v[r][1].x * m, v[r][1].y * m);
                        }
                    }
                }
            }
        }
    }
}

extern "C" void kernel_launch(void* const* d_in, const int* in_sizes, int n_in,
                              void* d_out, int out_size) {
    (void)in_sizes; (void)n_in; (void)out_size;
    const float* act = (const float*)d_in[0];
    float* out = (float*)d_out;
    block_relu_kernel<<<2048, 256>>>(act, out);
}

// round 4
// speedup vs baseline: 1.0613x; 1.0613x over previous
#include <cuda_runtime.h>
#include <cuda_bf16.h>
#include <cstdint>

// activation (16, 128, 114, 114) float32.
// Channels  0..31  : inactive (copy)
// Channels 32..79  : 2x2 block-sign ReLU
// Channels 80..127 : 4x4 block-sign ReLU
//
// Sign chain (exact): s = int64(trunc(f32 block sum)); mean = s >> log2(n);
//                     sign = int16(mean >> 5) >= 0; out = in * sign
//
// Strategy: TMA (cp.async.bulk) streaming. Each CTA owns one quarter-image
// chunk (rows split at 0/28/56/84 — multiples of 4, so no 2x2 or 4x4 block
// straddles a chunk). Bulk-load global->smem, compute signs and multiply
// in-place in smem, bulk-store smem->global. MLP comes from the bulk engine
// + 16 CTAs/SM in different pipeline phases, not from per-thread batching.

#define W_DIM 114
#define H_DIM 114
#define IMG_ELEMS (H_DIM * W_DIM)        // 12996 floats, 51984 B (16B-mult)
#define MAX_CHUNK_FLOATS (30 * W_DIM)    // 3420 floats = 13680 B

__device__ __forceinline__ float sgn4(float sum)  {  // 2x2: n=4
    long long s = (long long)sum;                    // trunc toward zero
    short q = (short)((s >> 2) >> 5);
    return (q >= 0) ? 1.0f : 0.0f;
}
__device__ __forceinline__ float sgn16(float sum) {  // 4x4: n=16
    long long s = (long long)sum;
    short q = (short)((s >> 4) >> 5);
    return (q >= 0) ? 1.0f : 0.0f;
}

__global__ void __launch_bounds__(128)
block_relu_tma(const float* __restrict__ in, float* __restrict__ out) {
    __shared__ alignas(128) float buf[MAX_CHUNK_FLOATS];
    __shared__ alignas(8) uint64_t mbar;

    const int q    = blockIdx.x & 3;
    const int img  = blockIdx.x >> 2;    // n*128 + c
    const int c    = img & 127;
    const int row0 = q * 28;
    const int nrows = (q == 3) ? 30 : 28;
    const int bytes = nrows * W_DIM * 4; // 12768 or 13680, both 16B-mult

    const float* src = in  + (size_t)img * IMG_ELEMS + (size_t)row0 * W_DIM;
    float*       dst = out + (size_t)img * IMG_ELEMS + (size_t)row0 * W_DIM;

    const int t = threadIdx.x;
    const uint32_t mb = (uint32_t)__cvta_generic_to_shared(&mbar);
    const uint32_t sb = (uint32_t)__cvta_generic_to_shared(buf);

    if (t == 0) {
        asm volatile("mbarrier.init.shared.b64 [%0], 1;" :: "r"(mb) : "memory");
    }
    __syncthreads();
    if (t == 0) {
        asm volatile("mbarrier.arrive.expect_tx.shared.b64 _, [%0], %1;"
                     :: "r"(mb), "r"(bytes) : "memory");
        asm volatile("cp.async.bulk.shared::cta.global.mbarrier::complete_tx::bytes "
                     "[%0], [%1], %2, [%3];"
                     :: "r"(sb), "l"(src), "r"(bytes), "r"(mb) : "memory");
    }

    // All threads wait for the bulk load to land.
    {
        uint32_t done;
        do {
            asm volatile(
                "{\n\t.reg .pred P;\n\t"
                "mbarrier.try_wait.parity.shared::cta.b64 P, [%1], %2, 0x989680;\n\t"
                "selp.b32 %0, 1, 0, P;\n\t}"
                : "=r"(done) : "r"(mb), "r"(0u) : "memory");
        } while (!done);
    }

    if (c >= 32 && c < 80) {
        // ---- 2x2 blocks on this chunk: (nrows/2) block rows x 57 blocks ----
        const int nbr = nrows >> 1;          // 14 or 15
        const int total = nbr * 57;
        for (int i = t; i < total; i += 128) {
            const int bi = i / 57;
            const int bj = i - bi * 57;
            float* p0 = buf + (2 * bi) * W_DIM + 2 * bj;
            float* p1 = p0 + W_DIM;
            float2 a = *(float2*)p0;
            float2 b = *(float2*)p1;
            const float m = sgn4(a.x + a.y + b.x + b.y);
            *(float2*)p0 = make_float2(a.x * m, a.y * m);
            *(float2*)p1 = make_float2(b.x * m, b.y * m);
        }
    } else if (c >= 80) {
        // ---- 4x4 blocks: 7 (or 8, last partial 2-row) block rows x 29 ----
        const int nb4 = (nrows + 3) >> 2;    // 7 or 8
        const int total = nb4 * 29;
        for (int i = t; i < total; i += 128) {
            const int bi = i / 29;
            const int bj = i - bi * 29;
            const int lr0 = 4 * bi;
            const int avail = min(4, nrows - lr0);      // 4, or 2 on last row q3
            const int c0 = 4 * bj;
            const int ncols = (c0 + 4 <= W_DIM) ? 4 : 2;
            float sum = 0.0f;
            // row-major sequential accumulation (matches reference order used so far)
            for (int r = 0; r < avail; r++) {
                float* p = buf + (lr0 + r) * W_DIM + c0;
                for (int cc = 0; cc < ncols; cc++) sum += p[cc];
            }
            const float m = sgn16(sum);
            for (int r = 0; r < avail; r++) {
                float* p = buf + (lr0 + r) * W_DIM + c0;
                for (int cc = 0; cc < ncols; cc++) p[cc] *= m;
            }
        }
    }
    // c < 32: pure copy-through, smem already holds the data.

    __syncthreads();
    if (t == 0) {
        // Order generic-proxy smem writes before the async-proxy bulk store.
        asm volatile("fence.proxy.async.shared::cta;" ::: "memory");
        asm volatile("cp.async.bulk.global.shared::cta.bulk_group [%0], [%1], %2;"
                     :: "l"(dst), "r"(sb), "r"(bytes) : "memory");
        asm volatile("cp.async.bulk.commit_group;" ::: "memory");
        asm volatile("cp.async.bulk.wait_group 0;" ::: "memory");
    }
}

extern "C" void kernel_launch(void* const* d_in, const int* in_sizes, int n_in,
                              void* d_out, int out_size) {
    (void)in_sizes; (void)n_in; (void)out_size;
    const float* act = (const float*)d_in[0];
    float* out = (float*)d_out;
    // 16 batches * 128 channels * 4 quarter-chunks = 8192 CTAs
    block_relu_tma<<<8192, 128>>>(act, out);
}

// round 5
// speedup vs baseline: 1.1190x; 1.0544x over previous
#include <cuda_runtime.h>
#include <cuda_bf16.h>
#include <cstdint>

// activation (16, 128, 114, 114) float32.
// Channels  0..31  : inactive (copy)      — TMA load + TMA store (no thread work)
// Channels 32..79  : 2x2 block-sign ReLU  — TMA load + LDS + STG
// Channels 80..127 : 4x4 block-sign ReLU  — TMA load + LDS + STG
//
// Sign chain (exact): s = int64(trunc(f32 block sum)); mean = s >> log2(n);
//                     sign = int16(mean >> 5) >= 0; out = in * sign
//
// Chunking: quarter images, rows split at 0/28/56/84 (multiples of 4 -> no
// block straddles a chunk; chunk byte sizes are multiples of 16 for TMA).

#define W_DIM 114
#define H_DIM 114
#define IMG_ELEMS (H_DIM * W_DIM)        // 12996 floats, 51984 B
#define MAX_CHUNK_FLOATS (30 * W_DIM)    // 3420 floats = 13680 B

__device__ __forceinline__ float sgn4(float sum)  {  // 2x2
    long long s = (long long)sum;
    short q = (short)((s >> 2) >> 5);
    return (q >= 0) ? 1.0f : 0.0f;
}
__device__ __forceinline__ float sgn16(float sum) {  // 4x4
    long long s = (long long)sum;
    short q = (short)((s >> 4) >> 5);
    return (q >= 0) ? 1.0f : 0.0f;
}

__global__ void __launch_bounds__(128)
block_relu_tma(const float* __restrict__ in, float* __restrict__ out) {
    __shared__ alignas(128) float buf[MAX_CHUNK_FLOATS];
    __shared__ alignas(8) uint64_t mbar;

    const int q    = blockIdx.x & 3;
    const int img  = blockIdx.x >> 2;    // n*128 + c
    const int c    = img & 127;
    const int row0 = q * 28;             // even -> chunk-local row parity == global parity
    const int nrows = (q == 3) ? 30 : 28;
    const int bytes = nrows * W_DIM * 4;

    const float* src = in  + (size_t)img * IMG_ELEMS + (size_t)row0 * W_DIM;
    float*       dst = out + (size_t)img * IMG_ELEMS + (size_t)row0 * W_DIM;

    const int t = threadIdx.x;
    const uint32_t mb = (uint32_t)__cvta_generic_to_shared(&mbar);
    const uint32_t sb = (uint32_t)__cvta_generic_to_shared(buf);

    if (t == 0) {
        asm volatile("mbarrier.init.shared.b64 [%0], 1;" :: "r"(mb) : "memory");
    }
    __syncthreads();
    if (t == 0) {
        asm volatile("mbarrier.arrive.expect_tx.shared.b64 _, [%0], %1;"
                     :: "r"(mb), "r"(bytes) : "memory");
        asm volatile("cp.async.bulk.shared::cta.global.mbarrier::complete_tx::bytes "
                     "[%0], [%1], %2, [%3];"
                     :: "r"(sb), "l"(src), "r"(bytes), "r"(mb) : "memory");
    }

    if (c < 32) {
        // ---- copy-through: only t0 needs the data landed; bulk store back ----
        if (t == 0) {
            uint32_t done;
            do {
                asm volatile(
                    "{\n\t.reg .pred P;\n\t"
                    "mbarrier.try_wait.parity.shared::cta.b64 P, [%1], %2, 0x989680;\n\t"
                    "selp.b32 %0, 1, 0, P;\n\t}"
                    : "=r"(done) : "r"(mb), "r"(0u) : "memory");
            } while (!done);
            asm volatile("fence.proxy.async.shared::cta;" ::: "memory");
            asm volatile("cp.async.bulk.global.shared::cta.bulk_group [%0], [%1], %2;"
                         :: "l"(dst), "r"(sb), "r"(bytes) : "memory");
            asm volatile("cp.async.bulk.commit_group;" ::: "memory");
            asm volatile("cp.async.bulk.wait_group 0;" ::: "memory");
        }
        return;
    }

    // active channels: all threads wait for the bulk load
    {
        uint32_t done;
        do {
            asm volatile(
                "{\n\t.reg .pred P;\n\t"
                "mbarrier.try_wait.parity.shared::cta.b64 P, [%1], %2, 0x989680;\n\t"
                "selp.b32 %0, 1, 0, P;\n\t}"
                : "=r"(done) : "r"(mb), "r"(0u) : "memory");
        } while (!done);
    }

    if (c < 80) {
        // ---- 2x2: (nrows/2) block rows x 57 blocks; LDS.64 + STG.64 ----
        const int nbr = nrows >> 1;          // 14 or 15
        const int total = nbr * 57;
        #pragma unroll 2
        for (int i = t; i < total; i += 128) {
            const int bi = i / 57;
            const int bj = i - bi * 57;
            const int off = (2 * bi) * W_DIM + 2 * bj;
            float2 a = *(const float2*)(buf + off);
            float2 b = *(const float2*)(buf + off + W_DIM);
            const float m = sgn4(a.x + a.y + b.x + b.y);
            *(float2*)(dst + off)         = make_float2(a.x * m, a.y * m);
            *(float2*)(dst + off + W_DIM) = make_float2(b.x * m, b.y * m);
        }
    } else {
        // ---- 4x4: block rows x 29 blocks; even rows float4, odd rows float2 ----
        const int nb4 = (nrows + 3) >> 2;    // 7 or 8 (q3 last block row has 2 rows)
        const int total = nb4 * 29;
        for (int i = t; i < total; i += 128) {
            const int bi = i / 29;
            const int bj = i - bi * 29;
            const int lr0 = 4 * bi;                       // even
            const int avail = min(4, nrows - lr0);        // 4, or 2 (q3 tail)
            const int c0 = 4 * bj;
            const bool fullc = (c0 + 4 <= W_DIM);         // bj==28 -> 2 cols

            if (fullc && avail == 4) {
                const float* p = buf + lr0 * W_DIM + c0;
                float4 v0 = *(const float4*)(p);                 // even row: 16B aligned
                float2 v1a = *(const float2*)(p + W_DIM);
                float2 v1b = *(const float2*)(p + W_DIM + 2);
                float4 v2 = *(const float4*)(p + 2 * W_DIM);
                float2 v3a = *(const float2*)(p + 3 * W_DIM);
                float2 v3b = *(const float2*)(p + 3 * W_DIM + 2);
                float sum = v0.x + v0.y + v0.z + v0.w
                          + v1a.x + v1a.y + v1b.x + v1b.y
                          + v2.x + v2.y + v2.z + v2.w
                          + v3a.x + v3a.y + v3b.x + v3b.y;
                const float m = sgn16(sum);
                float* d = dst + lr0 * W_DIM + c0;
                *(float4*)(d)             = make_float4(v0.x*m, v0.y*m, v0.z*m, v0.w*m);
                *(float2*)(d + W_DIM)     = make_float2(v1a.x*m, v1a.y*m);
                *(float2*)(d + W_DIM + 2) = make_float2(v1b.x*m, v1b.y*m);
                *(float4*)(d + 2 * W_DIM) = make_float4(v2.x*m, v2.y*m, v2.z*m, v2.w*m);
                *(float2*)(d + 3 * W_DIM)     = make_float2(v3a.x*m, v3a.y*m);
                *(float2*)(d + 3 * W_DIM + 2) = make_float2(v3b.x*m, v3b.y*m);
            } else {
                const int ncols = fullc ? 4 : 2;
                float v[4][4];
                float sum = 0.0f;
                for (int r = 0; r < avail; r++) {
                    const float* p = buf + (lr0 + r) * W_DIM + c0;
                    for (int cc = 0; cc < ncols; cc++) { v[r][cc] = p[cc]; sum += v[r][cc]; }
                }
                const float m = sgn16(sum);
                for (int r = 0; r < avail; r++) {
                    float* d = dst + (lr0 + r) * W_DIM + c0;
                    for (int cc = 0; cc < ncols; cc++) d[cc] = v[r][cc] * m;
                }
            }
        }
    }
}

extern "C" void kernel_launch(void* const* d_in, const int* in_sizes, int n_in,
                              void* d_out, int out_size) {
    (void)in_sizes; (void)n_in; (void)out_size;
    const float* act = (const float*)d_in[0];
    float* out = (float*)d_out;
    block_relu_tma<<<8192, 128>>>(act, out);
}